// round 6
// baseline (speedup 1.0000x reference)
#include <cuda_runtime.h>

// GNN critic encoder, fully fused: one CTA per batch row.
// R5: f32x2 packed FMA + warp-per-head mapping + feature-major activations.

#define HSTRIDE 1032   // h2 per-head stride (words); 1032 % 32 == 8
#define XTS 36         // xt per-feature stride (words); 36 % 4 == 0 (16B align), %32==4

typedef unsigned long long ull;

__device__ __forceinline__ ull fma2(ull a, ull b, ull c) {
    ull d;
    asm("fma.rn.f32x2 %0, %1, %2, %3;" : "=l"(d) : "l"(a), "l"(b), "l"(c));
    return d;
}
__device__ __forceinline__ ull pack2(float lo, float hi) {
    ull r;
    asm("mov.b64 %0, {%1, %2};" : "=l"(r) : "f"(lo), "f"(hi));
    return r;
}
__device__ __forceinline__ void unpack2(ull v, float& lo, float& hi) {
    asm("mov.b64 {%0, %1}, %2;" : "=f"(lo), "=f"(hi) : "l"(v));
}
__device__ __forceinline__ ull dup2(float v) { return pack2(v, v); }

__device__ __forceinline__ float elu1(float v) { return v > 0.f ? v : expm1f(v); }

// Token embedding -> xt (feature-major). Cols per thread: lane, lane+32, lane+64, lane+96.
template<int D>
__device__ __forceinline__ void embed_tokens(const float* __restrict__ obs_tok,
                                             const float* __restrict__ W,
                                             const float* __restrict__ bias,
                                             float* __restrict__ xt,
                                             int t0, int lane)
{
    float bb[4];
#pragma unroll
    for (int c = 0; c < 4; c++) bb[c] = __ldg(&bias[lane + 32 * c]);
    float acc[8][4];
#pragma unroll
    for (int r = 0; r < 8; r++)
#pragma unroll
        for (int c = 0; c < 4; c++) acc[r][c] = bb[c];
#pragma unroll 4
    for (int d = 0; d < D; d++) {
        float wv[4];
#pragma unroll
        for (int c = 0; c < 4; c++) wv[c] = __ldg(&W[d * 128 + lane + 32 * c]);
#pragma unroll
        for (int r = 0; r < 8; r++) {
            float xv = obs_tok[r * D + d];
#pragma unroll
            for (int c = 0; c < 4; c++) acc[r][c] += xv * wv[c];
        }
    }
#pragma unroll
    for (int r = 0; r < 8; r++)
#pragma unroll
        for (int c = 0; c < 4; c++)
            xt[(lane + 32 * c) * XTS + (t0 + r)] = acc[r][c];
}

__global__ __launch_bounds__(128, 4)
void gnn_critic_kernel(const float* __restrict__ gobs,
                       const float* __restrict__ Wv, const float* __restrict__ bv,
                       const float* __restrict__ Wp, const float* __restrict__ bp,
                       const float* __restrict__ w0g, const float* __restrict__ as0,
                       const float* __restrict__ ad0,
                       const float* __restrict__ w1g, const float* __restrict__ as1,
                       const float* __restrict__ ad1,
                       float* __restrict__ out)
{
    __shared__ float xt[128 * XTS];          // activations, feature-major [f][token]
    __shared__ float h2[4 * HSTRIDE];        // h = x @ w, head-strided [head][token*32+d]
    __shared__ ull   wstage[2048];           // 16x128 k-block, values pre-duplicated {w,w}
    __shared__ float as_sh[128];             // [head*32 + token]
    __shared__ float ad_sh[128];
    __shared__ float alive[32];
    __shared__ float inv_cnt_sh;

    float* obs = (float*)wstage;             // 1056 floats <= 4096; consumed before staging

    const int tid  = threadIdx.x;
    const int lane = tid & 31;
    const int warp = tid >> 5;               // == head for GEMM/attention phases
    const int b    = blockIdx.x;

    // ---- load obs row ----
    const float* rowp = gobs + (long)b * 1056;
    for (int i = tid; i < 1056; i += 128) obs[i] = __ldg(&rowp[i]);
    __syncthreads();

    // ---- alive mask + all-dead fix + pool count ----
    if (warp == 0) {
        float v = (obs[1024 + lane] >= 0.5f) ? 1.0f : 0.0f;
        float s = v;
#pragma unroll
        for (int o = 16; o; o >>= 1) s += __shfl_xor_sync(0xffffffffu, s, o);
        float vv = (s < 0.5f) ? 1.0f : v;
        alive[lane] = vv;
        if (lane == 0) {
            float cnt = (s < 0.5f) ? 32.0f : s;
            inv_cnt_sh = 1.0f / fmaxf(cnt, 1.0f);
        }
    }
    __syncthreads();

    // ---- token embedding: warps 0-1 vehicles (D=40), warps 2-3 peds (D=24) ----
    if (warp < 2)
        embed_tokens<40>(obs + warp * 8 * 40, Wv, bv, xt, warp * 8, lane);
    else
        embed_tokens<24>(obs + 640 + (warp - 2) * 8 * 24, Wp, bp, xt, warp * 8, lane);
    __syncthreads();

    const int lq = lane & 7;                 // col quad within head: cols lq*4..lq*4+3
    const int t0 = (lane >> 3) * 8;          // row (token) base: 8 rows per lane

    for (int L = 0; L < 2; L++) {
        const float* w    = L ? w1g : w0g;
        const float* asrc = L ? as1 : as0;
        const float* adst = L ? ad1 : ad0;

        // ---- GEMM: h = x @ w. warp = head (32 cols), f32x2 over token pairs ----
        ull acc[4][4];                       // [rowpair][col] : rows (t0+2rp, t0+2rp+1)
#pragma unroll
        for (int rp = 0; rp < 4; rp++)
#pragma unroll
            for (int c = 0; c < 4; c++) acc[rp][c] = 0ull;

        for (int kb = 0; kb < 8; kb++) {
            __syncthreads();                 // previous wstage readers done (or obs consumed)
#pragma unroll
            for (int j = 0; j < 16; j++) {
                float v = __ldg(&w[kb * 2048 + j * 128 + tid]);
                wstage[j * 128 + tid] = dup2(v);   // pre-duplicated multiplier
            }
            __syncthreads();
#pragma unroll 4
            for (int kk = 0; kk < 16; kk++) {
                const int k = kb * 16 + kk;
                const ulonglong2* xp = (const ulonglong2*)&xt[k * XTS + t0];
                ulonglong2 xa = xp[0];       // token pairs (t0,t0+1),(t0+2,t0+3)
                ulonglong2 xb = xp[1];       // (t0+4,t0+5),(t0+6,t0+7)
                const ulonglong2* wp = (const ulonglong2*)&wstage[kk * 128 + warp * 32 + lq * 4];
                ulonglong2 wa = wp[0];       // cols lq*4, lq*4+1 (dup'd)
                ulonglong2 wb = wp[1];       // cols lq*4+2, lq*4+3
                acc[0][0] = fma2(wa.x, xa.x, acc[0][0]);
                acc[0][1] = fma2(wa.y, xa.x, acc[0][1]);
                acc[0][2] = fma2(wb.x, xa.x, acc[0][2]);
                acc[0][3] = fma2(wb.y, xa.x, acc[0][3]);
                acc[1][0] = fma2(wa.x, xa.y, acc[1][0]);
                acc[1][1] = fma2(wa.y, xa.y, acc[1][1]);
                acc[1][2] = fma2(wb.x, xa.y, acc[1][2]);
                acc[1][3] = fma2(wb.y, xa.y, acc[1][3]);
                acc[2][0] = fma2(wa.x, xb.x, acc[2][0]);
                acc[2][1] = fma2(wa.y, xb.x, acc[2][1]);
                acc[2][2] = fma2(wb.x, xb.x, acc[2][2]);
                acc[2][3] = fma2(wb.y, xb.x, acc[2][3]);
                acc[3][0] = fma2(wa.x, xb.y, acc[3][0]);
                acc[3][1] = fma2(wa.y, xb.y, acc[3][1]);
                acc[3][2] = fma2(wb.x, xb.y, acc[3][2]);
                acc[3][3] = fma2(wb.y, xb.y, acc[3][3]);
            }
        }
        // write h2 (head-strided, token-major rows) as float4 per row
#pragma unroll
        for (int rp = 0; rp < 4; rp++) {
            float lo0, hi0, lo1, hi1, lo2, hi2, lo3, hi3;
            unpack2(acc[rp][0], lo0, hi0);
            unpack2(acc[rp][1], lo1, hi1);
            unpack2(acc[rp][2], lo2, hi2);
            unpack2(acc[rp][3], lo3, hi3);
            float* base = &h2[warp * HSTRIDE + (t0 + 2 * rp) * 32 + lq * 4];
            *(float4*)base          = make_float4(lo0, lo1, lo2, lo3);
            *(float4*)(base + 32)   = make_float4(hi0, hi1, hi2, hi3);
        }
        __syncthreads();

        // ---- alpha_src / alpha_dst : warp = head, lane = token ----
        {
            const float* hrow = &h2[warp * HSTRIDE + lane * 32];
            float sa = 0.f, sd = 0.f;
#pragma unroll
            for (int q = 0; q < 8; q++) {
                const int d4 = (q + lane) & 7;       // XOR-rotate: conflict-free
                float4 hv = *(const float4*)&hrow[d4 * 4];
                float4 a1 = __ldg((const float4*)&asrc[warp * 32 + d4 * 4]);
                float4 a2 = __ldg((const float4*)&adst[warp * 32 + d4 * 4]);
                sa += hv.x * a1.x + hv.y * a1.y + hv.z * a1.z + hv.w * a1.w;
                sd += hv.x * a2.x + hv.y * a2.y + hv.z * a2.z + hv.w * a2.w;
            }
            as_sh[warp * 32 + lane] = sa;
            ad_sh[warp * 32 + lane] = sd;
        }
        __syncthreads();

        // ---- attention + aggregate + ELU : warp = head, lane = query i ----
        {
            const int i = lane;
            const float a_i = as_sh[warp * 32 + i];
            float p[32];
            float m = -1e30f;
#pragma unroll
            for (int j = 0; j < 32; j++) {
                float e = a_i + ad_sh[warp * 32 + j];   // broadcast
                e = fmaxf(e, 0.2f * e);                 // leaky relu
                p[j] = (alive[j] > 0.5f) ? e : -1e30f;  // mask
                m = fmaxf(m, p[j]);
            }
            float s = 0.f;
#pragma unroll
            for (int j = 0; j < 32; j++) { p[j] = __expf(p[j] - m); s += p[j]; }
            const float inv = 1.0f / s;

            const ulonglong2* hb = (const ulonglong2*)&h2[warp * HSTRIDE];
            ull agg[16];
#pragma unroll
            for (int d = 0; d < 16; d++) agg[d] = 0ull;
#pragma unroll 2
            for (int j = 0; j < 32; j++) {
                ull pj = dup2(p[j]);
#pragma unroll
                for (int d2 = 0; d2 < 8; d2++) {
                    ulonglong2 hv = hb[j * 8 + d2];     // pure broadcast, 16B
                    agg[2 * d2]     = fma2(pj, hv.x, agg[2 * d2]);
                    agg[2 * d2 + 1] = fma2(pj, hv.y, agg[2 * d2 + 1]);
                }
            }
            // normalize + ELU, store feature-major for next GEMM / pool
#pragma unroll
            for (int d2 = 0; d2 < 8; d2++) {
                float v0, v1, v2, v3;
                unpack2(agg[2 * d2],     v0, v1);
                unpack2(agg[2 * d2 + 1], v2, v3);
                v0 = elu1(v0 * inv); v1 = elu1(v1 * inv);
                v2 = elu1(v2 * inv); v3 = elu1(v3 * inv);
                const int f = warp * 32 + d2 * 4;
                xt[(f + 0) * XTS + i] = v0;             // conflict-free: lanes span banks
                xt[(f + 1) * XTS + i] = v1;
                xt[(f + 2) * XTS + i] = v2;
                xt[(f + 3) * XTS + i] = v3;
            }
        }
        __syncthreads();
    }

    // ---- masked mean pool: thread = output feature ----
    {
        float s = 0.f;
        const float* xf = &xt[tid * XTS];
#pragma unroll
        for (int i = 0; i < 32; i++)
            s += alive[i] * xf[i];
        out[(long)b * 128 + tid] = s * inv_cnt_sh;
    }
}

extern "C" void kernel_launch(void* const* d_in, const int* in_sizes, int n_in,
                              void* d_out, int out_size)
{
    const float* gobs = (const float*)d_in[0];
    const float* Wv   = (const float*)d_in[1];
    const float* bv   = (const float*)d_in[2];
    const float* Wp   = (const float*)d_in[3];
    const float* bp   = (const float*)d_in[4];
    const float* w0   = (const float*)d_in[5];
    const float* as0  = (const float*)d_in[6];
    const float* ad0  = (const float*)d_in[7];
    const float* w1   = (const float*)d_in[8];
    const float* as1  = (const float*)d_in[9];
    const float* ad1  = (const float*)d_in[10];

    const int B = in_sizes[0] / 1056;

    gnn_critic_kernel<<<B, 128>>>(gobs, Wv, bv, Wp, bp,
                                  w0, as0, ad0, w1, as1, ad1,
                                  (float*)d_out);
}